// round 2
// baseline (speedup 1.0000x reference)
#include <cuda_runtime.h>
#include <math.h>

#define CD 1024
#define LD 80
#define WDIM 300
#define HW 196
#define BT 4
#define NP 784
#define OD 2048
#define NE (BT*LD*CD)

#define BM 32
#define BN 64
#define BK 16

#define MODE_NONE   0
#define MODE_SIG    1
#define MODE_SIGMUL 2
#define MODE_GRU    3
#define MODE_TANH   4

__device__ float d_fwd[LD*CD];
__device__ float d_v[CD];
__device__ float d_c0s[1];
__device__ float d_bz[CD];
__device__ float d_br[CD];
__device__ float d_bh[CD];
__device__ float d_w3s[CD*CD];
__device__ float d_w4s[CD*CD];
__device__ float d_w5s[CD*CD];
__device__ float d_fwh[NP*CD];
__device__ float d_coeff[NP*LD];
__device__ float d_g[NE];
__device__ float d_nodes[NE];
__device__ float d_abuf[NE];
__device__ float d_zbuf[NE];
__device__ float d_rn[NE];

__global__ void k_wsum(const float* __restrict__ w3, const float* __restrict__ w4,
                       const float* __restrict__ w5) {
    const int T = CD*CD;
    int stride = gridDim.x * blockDim.x;
    for (int i = blockIdx.x*blockDim.x + threadIdx.x; i < 3*T; i += stride) {
        int which = i / T;
        int rem = i - which*T;
        int r = rem >> 10, c = rem & (CD-1);
        const float* w = (which==0) ? w3 : (which==1) ? w4 : w5;
        float val = w[r*2*CD + c] + w[r*2*CD + CD + c];
        float* o = (which==0) ? d_w3s : (which==1) ? d_w4s : d_w5s;
        o[rem] = val;
    }
}

__global__ void k_bias(const float* __restrict__ b3, const float* __restrict__ u3b,
                       const float* __restrict__ b4, const float* __restrict__ b5,
                       const float* __restrict__ u5b) {
    int i = blockIdx.x*256 + threadIdx.x;
    if (i < CD) {
        d_bz[i] = b3[i] + u3b[i];
        d_br[i] = b4[i] + u3b[i];
        d_bh[i] = b5[i] + u5b[i];
    }
}

__global__ void k_v(const float* __restrict__ fc3_w, const float* __restrict__ fca_w) {
    __shared__ float fs[CD];
    for (int j = threadIdx.x; j < CD; j += 256) fs[j] = fca_w[j];
    __syncthreads();
    int i = blockIdx.x*256 + threadIdx.x;
    float acc = 0.f;
    #pragma unroll 8
    for (int j = 0; j < CD; ++j) acc += fs[j] * fc3_w[j*CD + i];
    d_v[i] = acc;
}

__global__ void k_c0(const float* __restrict__ fc3_b, const float* __restrict__ fca_w,
                     const float* __restrict__ fca_b) {
    __shared__ float red[8];
    float acc = 0.f;
    for (int j = threadIdx.x; j < CD; j += 256) acc += fc3_b[j] * fca_w[j];
    #pragma unroll
    for (int o = 16; o > 0; o >>= 1) acc += __shfl_xor_sync(0xffffffffu, acc, o);
    if ((threadIdx.x & 31) == 0) red[threadIdx.x >> 5] = acc;
    __syncthreads();
    if (threadIdx.x == 0) {
        float s = 0.f;
        #pragma unroll
        for (int q = 0; q < 8; ++q) s += red[q];
        d_c0s[0] = s + fca_b[0];
    }
}

__global__ __launch_bounds__(128) void k_gemm(
    const float* __restrict__ A, int lda,
    const float* __restrict__ B, int ldb,
    const float* __restrict__ A2, int lda2,
    const float* __restrict__ B2, int ldb2,
    int M, int N, int K,
    const float* __restrict__ bias,
    const float* __restrict__ aux1,
    const float* __restrict__ aux2,
    float* __restrict__ C, int ldc, int mode)
{
    __shared__ __align__(16) float As[BK][BM+4];
    __shared__ __align__(16) float Bs[BK][BN+4];
    const int t = threadIdx.x;
    const int tx = t & 15, ty = t >> 4;
    const int m0 = blockIdx.y * BM, n0 = blockIdx.x * BN;
    float acc[4][4] = {};

    const int rowA = t >> 2;
    const int kq = (t & 3) * 4;
    const bool full = (m0 + BM <= M) && (n0 + BN <= N) && ((K & (BK-1)) == 0);

    for (int pass = 0; pass < 2; ++pass) {
        const float* Ap = pass ? A2 : A;
        const float* Bp = pass ? B2 : B;
        if (Ap == nullptr) break;
        const int la = pass ? lda2 : lda;
        const int lb = pass ? ldb2 : ldb;
        for (int k0 = 0; k0 < K; k0 += BK) {
            if (full) {
                float4 av = *(const float4*)(Ap + (m0 + rowA)*la + k0 + kq);
                As[kq+0][rowA] = av.x; As[kq+1][rowA] = av.y;
                As[kq+2][rowA] = av.z; As[kq+3][rowA] = av.w;
                float4 b0v = *(const float4*)(Bp + (n0 + rowA)*lb + k0 + kq);
                Bs[kq+0][rowA] = b0v.x; Bs[kq+1][rowA] = b0v.y;
                Bs[kq+2][rowA] = b0v.z; Bs[kq+3][rowA] = b0v.w;
                float4 b1v = *(const float4*)(Bp + (n0 + rowA + 32)*lb + k0 + kq);
                Bs[kq+0][rowA+32] = b1v.x; Bs[kq+1][rowA+32] = b1v.y;
                Bs[kq+2][rowA+32] = b1v.z; Bs[kq+3][rowA+32] = b1v.w;
            } else {
                #pragma unroll
                for (int j = 0; j < 4; ++j) {
                    int k = k0 + kq + j;
                    int m = m0 + rowA;
                    As[kq+j][rowA] = (m < M && k < K) ? Ap[m*la + k] : 0.f;
                    int n1 = n0 + rowA;
                    Bs[kq+j][rowA] = (n1 < N && k < K) ? Bp[n1*lb + k] : 0.f;
                    int n2 = n0 + rowA + 32;
                    Bs[kq+j][rowA+32] = (n2 < N && k < K) ? Bp[n2*lb + k] : 0.f;
                }
            }
            __syncthreads();
            #pragma unroll
            for (int k = 0; k < BK; ++k) {
                float a0 = As[k][ty*4+0], a1 = As[k][ty*4+1];
                float a2 = As[k][ty*4+2], a3 = As[k][ty*4+3];
                float b0 = Bs[k][tx*4+0], b1 = Bs[k][tx*4+1];
                float b2 = Bs[k][tx*4+2], b3 = Bs[k][tx*4+3];
                acc[0][0] += a0*b0; acc[0][1] += a0*b1; acc[0][2] += a0*b2; acc[0][3] += a0*b3;
                acc[1][0] += a1*b0; acc[1][1] += a1*b1; acc[1][2] += a1*b2; acc[1][3] += a1*b3;
                acc[2][0] += a2*b0; acc[2][1] += a2*b1; acc[2][2] += a2*b2; acc[2][3] += a2*b3;
                acc[3][0] += a3*b0; acc[3][1] += a3*b1; acc[3][2] += a3*b2; acc[3][3] += a3*b3;
            }
            __syncthreads();
        }
    }

    #pragma unroll
    for (int i = 0; i < 4; ++i) {
        int m = m0 + ty*4 + i;
        if (m >= M) continue;
        #pragma unroll
        for (int j = 0; j < 4; ++j) {
            int n = n0 + tx*4 + j;
            if (n >= N) continue;
            float x = acc[i][j];
            int idx = m*ldc + n;
            if (mode == MODE_NONE) {
                C[idx] = x;
            } else if (mode == MODE_SIG) {
                x += bias[n]; C[idx] = 1.f/(1.f + expf(-x));
            } else if (mode == MODE_SIGMUL) {
                x += bias[n]; C[idx] = (1.f/(1.f + expf(-x))) * aux1[idx];
            } else if (mode == MODE_GRU) {
                x += bias[n];
                float hc = tanhf(x);
                float z = aux1[idx];
                C[idx] = (1.f - z)*aux2[idx] + z*hc;
            } else {
                x += bias[n]; C[idx] = tanhf(x);
            }
        }
    }
}

__global__ __launch_bounds__(256) void k_coeff() {
    __shared__ float fwh_s[CD];
    __shared__ float v_s[CD];
    int n = blockIdx.x;
    for (int i = threadIdx.x; i < CD; i += 256) {
        fwh_s[i] = d_fwh[n*CD + i];
        v_s[i]   = d_v[i];
    }
    __syncthreads();
    int warp = threadIdx.x >> 5, lane = threadIdx.x & 31;
    float c0 = d_c0s[0];
    for (int l = warp; l < LD; l += 8) {
        const float* fw = d_fwd + l*CD;
        float acc = 0.f;
        #pragma unroll 8
        for (int i = lane; i < CD; i += 32) {
            float p = fwh_s[i] * fw[i];
            float tv;
            asm("tanh.approx.f32 %0, %1;" : "=f"(tv) : "f"(p));
            acc += tv * v_s[i];
        }
        #pragma unroll
        for (int o = 16; o > 0; o >>= 1) acc += __shfl_xor_sync(0xffffffffu, acc, o);
        if (lane == 0) d_coeff[n*LD + l] = acc + c0;
    }
}

__global__ __launch_bounds__(256) void k_softmax() {
    int g = blockIdx.x*8 + (threadIdx.x >> 5);
    int lane = threadIdx.x & 31;
    if (g >= NP*LD/HW) return;
    float* p = d_coeff + g*HW;
    float vals[7];
    float mx = -1e30f;
    #pragma unroll
    for (int q = 0; q < 7; ++q) {
        int i = lane + q*32;
        vals[q] = (i < HW) ? p[i] : -1e30f;
        mx = fmaxf(mx, vals[q]);
    }
    #pragma unroll
    for (int o = 16; o > 0; o >>= 1) mx = fmaxf(mx, __shfl_xor_sync(0xffffffffu, mx, o));
    float s = 0.f;
    #pragma unroll
    for (int q = 0; q < 7; ++q) {
        int i = lane + q*32;
        if (i < HW) { vals[q] = expf(vals[q] - mx); s += vals[q]; }
    }
    #pragma unroll
    for (int o = 16; o > 0; o >>= 1) s += __shfl_xor_sync(0xffffffffu, s, o);
    float inv = 1.f / s;
    #pragma unroll
    for (int q = 0; q < 7; ++q) {
        int i = lane + q*32;
        if (i < HW) p[i] = vals[q]*inv;
    }
}

__global__ __launch_bounds__(256) void k_g(const float* __restrict__ img) {
    __shared__ float s[HW];
    int b = blockIdx.x / LD, l = blockIdx.x % LD;
    for (int tt = threadIdx.x; tt < HW; tt += 256)
        s[tt] = d_coeff[(b*HW + tt)*LD + l];
    __syncthreads();
    const float* xb = img + b*HW*CD;
    int c = threadIdx.x;
    float a0 = 0.f, a1 = 0.f, a2 = 0.f, a3 = 0.f;
    #pragma unroll 4
    for (int tt = 0; tt < HW; ++tt) {
        float w = s[tt];
        const float* xr = xb + tt*CD;
        a0 += w*xr[c]; a1 += w*xr[c+256]; a2 += w*xr[c+512]; a3 += w*xr[c+768];
    }
    float* go = d_g + (b*LD + l)*CD;
    go[c] = a0; go[c+256] = a1; go[c+512] = a2; go[c+768] = a3;
}

__global__ __launch_bounds__(256) void k_copy_g_nodes() {
    int i = blockIdx.x*256 + threadIdx.x;
    if (i < NE) d_nodes[i] = d_g[i];
}

__global__ __launch_bounds__(256) void k_a(const float* __restrict__ adj) {
    __shared__ float ar[LD];
    int b = blockIdx.x / LD, nn = blockIdx.x % LD;
    if (threadIdx.x < LD) ar[threadIdx.x] = adj[nn*LD + threadIdx.x];
    __syncthreads();
    int c = threadIdx.x;
    const float* nb = d_nodes + b*LD*CD;
    float a0 = 0.f, a1 = 0.f, a2 = 0.f, a3 = 0.f;
    #pragma unroll 4
    for (int m = 0; m < LD; ++m) {
        float w = ar[m];
        const float* nr = nb + m*CD;
        a0 += w*nr[c]; a1 += w*nr[c+256]; a2 += w*nr[c+512]; a3 += w*nr[c+768];
    }
    float* ao = d_abuf + (b*LD + nn)*CD;
    ao[c] = a0; ao[c+256] = a1; ao[c+512] = a2; ao[c+768] = a3;
}

static void gemm(const float* A, int lda, const float* B, int ldb,
                 const float* A2, int lda2, const float* B2, int ldb2,
                 int M, int N, int K,
                 const float* bias, const float* aux1, const float* aux2,
                 float* C, int ldc, int mode) {
    dim3 grid((N + BN - 1)/BN, (M + BM - 1)/BM);
    k_gemm<<<grid, 128>>>(A, lda, B, ldb, A2, lda2, B2, ldb2,
                          M, N, K, bias, aux1, aux2, C, ldc, mode);
}

extern "C" void kernel_launch(void* const* d_in, const int* in_sizes, int n_in,
                              void* d_out, int out_size) {
    const float* img  = (const float*)d_in[0];
    const float* wemb = (const float*)d_in[1];
    const float* adj  = (const float*)d_in[2];
    const float* fc1  = (const float*)d_in[3];
    const float* fc2  = (const float*)d_in[4];
    const float* fc3  = (const float*)d_in[5];
    const float* fc3b = (const float*)d_in[6];
    const float* fca  = (const float*)d_in[7];
    const float* fcab = (const float*)d_in[8];
    const float* w3   = (const float*)d_in[9];
    const float* b3   = (const float*)d_in[10];
    const float* u3   = (const float*)d_in[11];
    const float* u3b  = (const float*)d_in[12];
    const float* w4   = (const float*)d_in[13];
    const float* b4   = (const float*)d_in[14];
    const float* w5   = (const float*)d_in[15];
    const float* b5   = (const float*)d_in[16];
    const float* u5   = (const float*)d_in[17];
    const float* u5b  = (const float*)d_in[18];
    const float* fco  = (const float*)d_in[19];
    const float* fcob = (const float*)d_in[20];
    float* out = (float*)d_out;

    float *p_fwd, *p_w3s, *p_w4s, *p_w5s, *p_bz, *p_br, *p_bh;
    float *p_fwh, *p_g, *p_nodes, *p_a, *p_z, *p_rn;
    cudaGetSymbolAddress((void**)&p_fwd,   d_fwd);
    cudaGetSymbolAddress((void**)&p_w3s,   d_w3s);
    cudaGetSymbolAddress((void**)&p_w4s,   d_w4s);
    cudaGetSymbolAddress((void**)&p_w5s,   d_w5s);
    cudaGetSymbolAddress((void**)&p_bz,    d_bz);
    cudaGetSymbolAddress((void**)&p_br,    d_br);
    cudaGetSymbolAddress((void**)&p_bh,    d_bh);
    cudaGetSymbolAddress((void**)&p_fwh,   d_fwh);
    cudaGetSymbolAddress((void**)&p_g,     d_g);
    cudaGetSymbolAddress((void**)&p_nodes, d_nodes);
    cudaGetSymbolAddress((void**)&p_a,     d_abuf);
    cudaGetSymbolAddress((void**)&p_z,     d_zbuf);
    cudaGetSymbolAddress((void**)&p_rn,    d_rn);

    k_wsum<<<3072, 256>>>(w3, w4, w5);
    k_bias<<<4, 256>>>(b3, u3b, b4, b5, u5b);
    k_v<<<4, 256>>>(fc3, fca);
    k_c0<<<1, 256>>>(fc3b, fca, fcab);

    gemm(wemb, WDIM, fc2, WDIM, nullptr, 0, nullptr, 0,
         LD, CD, WDIM, nullptr, nullptr, nullptr, p_fwd, CD, MODE_NONE);
    gemm(img, CD, fc1, CD, nullptr, 0, nullptr, 0,
         NP, CD, CD, nullptr, nullptr, nullptr, p_fwh, CD, MODE_NONE);
    k_coeff<<<NP, 256>>>();
    k_softmax<<<40, 256>>>();
    k_g<<<BT*LD, 256>>>(img);

    k_copy_g_nodes<<<(NE + 255)/256, 256>>>();
    for (int step = 0; step < 3; ++step) {
        k_a<<<BT*LD, 256>>>(adj);
        gemm(p_a, CD, p_w3s, CD, p_nodes, CD, u3, CD,
             BT*LD, CD, CD, p_bz, nullptr, nullptr, p_z, CD, MODE_SIG);
        gemm(p_a, CD, p_w4s, CD, p_nodes, CD, u3, CD,
             BT*LD, CD, CD, p_br, p_nodes, nullptr, p_rn, CD, MODE_SIGMUL);
        gemm(p_a, CD, p_w5s, CD, p_rn, CD, u5, CD,
             BT*LD, CD, CD, p_bh, p_z, p_nodes, p_nodes, CD, MODE_GRU);
    }

    // out = tanh([nodes, g] @ fco^T + fco_b): dual-K over fco's two column halves
    gemm(p_nodes, CD, fco, OD, p_g, CD, fco + CD, OD,
         BT*LD, OD, CD, fcob, nullptr, nullptr, out, OD, MODE_TANH);
}

// round 3
// speedup vs baseline: 1.1080x; 1.1080x over previous
#include <cuda_runtime.h>
#include <math.h>

typedef unsigned long long ull;

#define CD 1024
#define LD 80
#define WDIM 300
#define HW 196
#define BT 4
#define NP 784
#define OD 2048
#define NE (BT*LD*CD)

#define BM 32
#define BN 64
#define BK 16
#define ASD 72   // 2*BM + 8 (duplicated A row)
#define BSD 68

#define MODE_NONE 0
#define MODE_ZRH  1
#define MODE_GRU2 2
#define MODE_TANH 3

// ---------------- scratch ----------------
__device__ float d_fwd[LD*CD];
__device__ float d_v[CD];
__device__ float d_c0s[1];
__device__ float d_ball[3*CD];
__device__ float d_wall[3*CD*CD];
__device__ float d_fwh[NP*CD];
__device__ float d_coeff[NP*LD];
__device__ float d_g[NE];
__device__ float d_nodes[NE];
__device__ float d_abuf[NE];
__device__ float d_zrh[BT*LD*3*CD];

// ---------------- f32x2 helpers ----------------
__device__ __forceinline__ ull fma2(ull a, ull b, ull c) {
    ull d;
    asm("fma.rn.f32x2 %0, %1, %2, %3;" : "=l"(d) : "l"(a), "l"(b), "l"(c));
    return d;
}
__device__ __forceinline__ ull pack2(float x, float y) {
    ull d;
    asm("mov.b64 %0, {%1, %2};" : "=l"(d) : "f"(x), "f"(y));
    return d;
}
__device__ __forceinline__ float2 unpack2(ull v) {
    float2 r;
    asm("mov.b64 {%0, %1}, %2;" : "=f"(r.x), "=f"(r.y) : "l"(v));
    return r;
}

// ---------------- prep kernels ----------------
__global__ void k_wsum(const float* __restrict__ w3, const float* __restrict__ w4,
                       const float* __restrict__ w5) {
    const int T = CD*CD;
    int stride = gridDim.x * blockDim.x;
    for (int i = blockIdx.x*blockDim.x + threadIdx.x; i < 3*T; i += stride) {
        int which = i / T;
        int rem = i - which*T;
        int r = rem >> 10, c = rem & (CD-1);
        const float* w = (which==0) ? w3 : (which==1) ? w4 : w5;
        d_wall[i] = w[r*2*CD + c] + w[r*2*CD + CD + c];
    }
}

__global__ void k_bias(const float* __restrict__ b3, const float* __restrict__ u3b,
                       const float* __restrict__ b4, const float* __restrict__ b5,
                       const float* __restrict__ u5b) {
    int i = blockIdx.x*256 + threadIdx.x;
    if (i < CD) {
        d_ball[i]        = b3[i] + u3b[i];
        d_ball[CD + i]   = b4[i] + u3b[i];   // reference reuses fc_eq3_u (torch bug, kept)
        d_ball[2*CD + i] = b5[i] + u5b[i];
    }
}

__global__ void k_v(const float* __restrict__ fc3_w, const float* __restrict__ fca_w) {
    __shared__ float fs[CD];
    for (int j = threadIdx.x; j < CD; j += 256) fs[j] = fca_w[j];
    __syncthreads();
    int i = blockIdx.x*256 + threadIdx.x;
    float acc = 0.f;
    #pragma unroll 8
    for (int j = 0; j < CD; ++j) acc += fs[j] * fc3_w[j*CD + i];
    d_v[i] = acc;
}

__global__ void k_c0(const float* __restrict__ fc3_b, const float* __restrict__ fca_w,
                     const float* __restrict__ fca_b) {
    __shared__ float red[8];
    float acc = 0.f;
    for (int j = threadIdx.x; j < CD; j += 256) acc += fc3_b[j] * fca_w[j];
    #pragma unroll
    for (int o = 16; o > 0; o >>= 1) acc += __shfl_xor_sync(0xffffffffu, acc, o);
    if ((threadIdx.x & 31) == 0) red[threadIdx.x >> 5] = acc;
    __syncthreads();
    if (threadIdx.x == 0) {
        float s = 0.f;
        #pragma unroll
        for (int q = 0; q < 8; ++q) s += red[q];
        d_c0s[0] = s + fca_b[0];
    }
}

// ---------------- GEMM: double-buffered, f32x2, dual-K, fused epilogues ----------------
template<int MODE>
__global__ __launch_bounds__(128) void k_gemm(
    const float* __restrict__ A, int lda,
    const float* __restrict__ B, int ldb,
    const float* __restrict__ A2, int lda2,
    const float* __restrict__ B2, int ldb2,
    int b2mask, int n2_limit,
    int M, int N, int K,
    const float* __restrict__ bias,
    const float* __restrict__ aux1,
    float* __restrict__ aux2,
    float* __restrict__ C, int ldc)
{
    __shared__ __align__(16) float As_s[2][BK][ASD];
    __shared__ __align__(16) float Bs_s[2][BK][BSD];

    const int t = threadIdx.x;
    const int tx = t & 15, ty = t >> 4;          // 16 x 8 thread grid; 4x4 microtile
    const int m0 = blockIdx.y * BM, n0 = blockIdx.x * BN;
    const int rowA = t >> 2;                     // 0..31
    const int kq = (t & 3) * 4;                  // 0,4,8,12

    const int ntiles1 = (K + BK - 1) / BK;
    const bool do2 = (A2 != nullptr) && (n0 < n2_limit);
    const int ntiles = do2 ? 2*ntiles1 : ntiles1;
    const bool full = (m0 + BM <= M) && (n0 + BN <= N) && ((K & (BK-1)) == 0);

    ull acc[4][2];
    #pragma unroll
    for (int i = 0; i < 4; ++i) { acc[i][0] = 0ull; acc[i][1] = 0ull; }

    float4 ra, rb0, rb1;

    auto load_tile = [&](int tt) {
        int pass = (tt >= ntiles1) ? 1 : 0;
        int k0 = (tt - pass*ntiles1) * BK;
        const float* Ap = pass ? A2 : A;
        const float* Bp = pass ? B2 : B;
        int la = pass ? lda2 : lda;
        int lb = pass ? ldb2 : ldb;
        int am = m0 + rowA;
        int bn1 = n0 + rowA, bn2 = n0 + rowA + 32;
        if (pass) { bn1 &= b2mask; bn2 &= b2mask; }
        int kk = k0 + kq;
        if (full) {
            ra  = *(const float4*)(Ap + (size_t)am*la + kk);
            rb0 = *(const float4*)(Bp + (size_t)bn1*lb + kk);
            rb1 = *(const float4*)(Bp + (size_t)bn2*lb + kk);
        } else {
            float a[4], b0[4], b1[4];
            #pragma unroll
            for (int j = 0; j < 4; ++j) {
                int k = kk + j;
                bool kok = (k < K);
                a[j]  = (am  < M && kok) ? Ap[(size_t)am*la + k]  : 0.f;
                b0[j] = (bn1 < N && kok) ? Bp[(size_t)bn1*lb + k] : 0.f;
                b1[j] = (bn2 < N && kok) ? Bp[(size_t)bn2*lb + k] : 0.f;
            }
            ra  = make_float4(a[0], a[1], a[2], a[3]);
            rb0 = make_float4(b0[0], b0[1], b0[2], b0[3]);
            rb1 = make_float4(b1[0], b1[1], b1[2], b1[3]);
        }
    };

    auto store_tile = [&](int bf) {
        // A stored duplicated as (v,v) pairs so compute reads LDS.64 with no packs
        *(ull*)&As_s[bf][kq+0][2*rowA] = pack2(ra.x, ra.x);
        *(ull*)&As_s[bf][kq+1][2*rowA] = pack2(ra.y, ra.y);
        *(ull*)&As_s[bf][kq+2][2*rowA] = pack2(ra.z, ra.z);
        *(ull*)&As_s[bf][kq+3][2*rowA] = pack2(ra.w, ra.w);
        Bs_s[bf][kq+0][rowA] = rb0.x; Bs_s[bf][kq+1][rowA] = rb0.y;
        Bs_s[bf][kq+2][rowA] = rb0.z; Bs_s[bf][kq+3][rowA] = rb0.w;
        Bs_s[bf][kq+0][rowA+32] = rb1.x; Bs_s[bf][kq+1][rowA+32] = rb1.y;
        Bs_s[bf][kq+2][rowA+32] = rb1.z; Bs_s[bf][kq+3][rowA+32] = rb1.w;
    };

    load_tile(0);
    store_tile(0);
    __syncthreads();
    int buf = 0;

    for (int tt = 0; tt < ntiles; ++tt) {
        if (tt + 1 < ntiles) load_tile(tt + 1);
        #pragma unroll
        for (int k = 0; k < BK; ++k) {
            ull b01 = *(const ull*)&Bs_s[buf][k][tx*4];
            ull b23 = *(const ull*)&Bs_s[buf][k][tx*4 + 2];
            ull a0 = *(const ull*)&As_s[buf][k][(ty*4+0)*2];
            ull a1 = *(const ull*)&As_s[buf][k][(ty*4+1)*2];
            ull a2 = *(const ull*)&As_s[buf][k][(ty*4+2)*2];
            ull a3 = *(const ull*)&As_s[buf][k][(ty*4+3)*2];
            acc[0][0] = fma2(a0, b01, acc[0][0]); acc[0][1] = fma2(a0, b23, acc[0][1]);
            acc[1][0] = fma2(a1, b01, acc[1][0]); acc[1][1] = fma2(a1, b23, acc[1][1]);
            acc[2][0] = fma2(a2, b01, acc[2][0]); acc[2][1] = fma2(a2, b23, acc[2][1]);
            acc[3][0] = fma2(a3, b01, acc[3][0]); acc[3][1] = fma2(a3, b23, acc[3][1]);
        }
        if (tt + 1 < ntiles) {
            store_tile(buf ^ 1);
            __syncthreads();
            buf ^= 1;
        }
    }

    // epilogue
    #pragma unroll
    for (int i = 0; i < 4; ++i) {
        int m = m0 + ty*4 + i;
        if (m >= M) continue;
        #pragma unroll
        for (int jp = 0; jp < 2; ++jp) {
            float2 v = unpack2(acc[i][jp]);
            #pragma unroll
            for (int s = 0; s < 2; ++s) {
                int n = n0 + tx*4 + jp*2 + s;
                if (n >= N) continue;
                float x = (s == 0) ? v.x : v.y;
                if (MODE == MODE_NONE) {
                    C[(size_t)m*ldc + n] = x;
                } else if (MODE == MODE_ZRH) {
                    x += bias[n];
                    float y;
                    if (n < CD)        y = 1.f/(1.f + expf(-x));                      // z
                    else if (n < 2*CD) y = (1.f/(1.f + expf(-x))) * aux1[m*CD + (n-CD)]; // r*nodes
                    else               y = x;                                          // h pre-act
                    C[(size_t)m*ldc + n] = y;
                } else if (MODE == MODE_GRU2) {
                    float ht   = aux1[m*3072 + 2048 + n];
                    float z    = aux1[m*3072 + n];
                    float prev = aux2[m*CD + n];
                    C[(size_t)m*ldc + n] = (1.f - z)*prev + z*tanhf(x + ht);
                } else { // MODE_TANH
                    x += bias[n];
                    C[(size_t)m*ldc + n] = tanhf(x);
                }
            }
        }
    }
}

// ---------------- semantic-branch kernels ----------------
__global__ __launch_bounds__(256) void k_coeff() {
    __shared__ float fwh_s[CD];
    __shared__ float v_s[CD];
    int n = blockIdx.x;
    for (int i = threadIdx.x; i < CD; i += 256) {
        fwh_s[i] = d_fwh[n*CD + i];
        v_s[i]   = d_v[i];
    }
    __syncthreads();
    int warp = threadIdx.x >> 5, lane = threadIdx.x & 31;
    float c0 = d_c0s[0];
    for (int l = warp; l < LD; l += 8) {
        const float* fw = d_fwd + l*CD;
        float acc = 0.f;
        #pragma unroll 8
        for (int i = lane; i < CD; i += 32) {
            float p = fwh_s[i] * fw[i];
            float tv;
            asm("tanh.approx.f32 %0, %1;" : "=f"(tv) : "f"(p));
            acc += tv * v_s[i];
        }
        #pragma unroll
        for (int o = 16; o > 0; o >>= 1) acc += __shfl_xor_sync(0xffffffffu, acc, o);
        if (lane == 0) d_coeff[n*LD + l] = acc + c0;
    }
}

__global__ __launch_bounds__(256) void k_softmax() {
    int g = blockIdx.x*8 + (threadIdx.x >> 5);
    int lane = threadIdx.x & 31;
    if (g >= NP*LD/HW) return;
    float* p = d_coeff + g*HW;
    float vals[7];
    float mx = -1e30f;
    #pragma unroll
    for (int q = 0; q < 7; ++q) {
        int i = lane + q*32;
        vals[q] = (i < HW) ? p[i] : -1e30f;
        mx = fmaxf(mx, vals[q]);
    }
    #pragma unroll
    for (int o = 16; o > 0; o >>= 1) mx = fmaxf(mx, __shfl_xor_sync(0xffffffffu, mx, o));
    float s = 0.f;
    #pragma unroll
    for (int q = 0; q < 7; ++q) {
        int i = lane + q*32;
        if (i < HW) { vals[q] = expf(vals[q] - mx); s += vals[q]; }
    }
    #pragma unroll
    for (int o = 16; o > 0; o >>= 1) s += __shfl_xor_sync(0xffffffffu, s, o);
    float inv = 1.f / s;
    #pragma unroll
    for (int q = 0; q < 7; ++q) {
        int i = lane + q*32;
        if (i < HW) p[i] = vals[q]*inv;
    }
}

// g[b,l,c] = sum_t coeff * img ; also seeds nodes = g
__global__ __launch_bounds__(256) void k_g(const float* __restrict__ img) {
    __shared__ float s[HW];
    int b = blockIdx.x / LD, l = blockIdx.x % LD;
    for (int tt = threadIdx.x; tt < HW; tt += 256)
        s[tt] = d_coeff[(b*HW + tt)*LD + l];
    __syncthreads();
    const float* xb = img + b*HW*CD;
    int c = threadIdx.x;
    float a0 = 0.f, a1 = 0.f, a2 = 0.f, a3 = 0.f;
    #pragma unroll 4
    for (int tt = 0; tt < HW; ++tt) {
        float w = s[tt];
        const float* xr = xb + tt*CD;
        a0 += w*xr[c]; a1 += w*xr[c+256]; a2 += w*xr[c+512]; a3 += w*xr[c+768];
    }
    float* go = d_g + (b*LD + l)*CD;
    float* no = d_nodes + (b*LD + l)*CD;
    go[c] = a0; go[c+256] = a1; go[c+512] = a2; go[c+768] = a3;
    no[c] = a0; no[c+256] = a1; no[c+512] = a2; no[c+768] = a3;
}

__global__ __launch_bounds__(256) void k_a(const float* __restrict__ adj) {
    __shared__ float ar[LD];
    int b = blockIdx.x / LD, nn = blockIdx.x % LD;
    if (threadIdx.x < LD) ar[threadIdx.x] = adj[nn*LD + threadIdx.x];
    __syncthreads();
    int c = threadIdx.x;
    const float* nb = d_nodes + b*LD*CD;
    float a0 = 0.f, a1 = 0.f, a2 = 0.f, a3 = 0.f;
    #pragma unroll 4
    for (int m = 0; m < LD; ++m) {
        float w = ar[m];
        const float* nr = nb + m*CD;
        a0 += w*nr[c]; a1 += w*nr[c+256]; a2 += w*nr[c+512]; a3 += w*nr[c+768];
    }
    float* ao = d_abuf + (b*LD + nn)*CD;
    ao[c] = a0; ao[c+256] = a1; ao[c+512] = a2; ao[c+768] = a3;
}

// ---------------- host ----------------
template<int MODE>
static void gemm(const float* A, int lda, const float* B, int ldb,
                 const float* A2, int lda2, const float* B2, int ldb2,
                 int b2mask, int n2_limit,
                 int M, int N, int K,
                 const float* bias, const float* aux1, float* aux2,
                 float* C, int ldc) {
    dim3 grid((N + BN - 1)/BN, (M + BM - 1)/BM);
    k_gemm<MODE><<<grid, 128>>>(A, lda, B, ldb, A2, lda2, B2, ldb2,
                                b2mask, n2_limit, M, N, K, bias, aux1, aux2, C, ldc);
}

extern "C" void kernel_launch(void* const* d_in, const int* in_sizes, int n_in,
                              void* d_out, int out_size) {
    const float* img  = (const float*)d_in[0];
    const float* wemb = (const float*)d_in[1];
    const float* adj  = (const float*)d_in[2];
    const float* fc1  = (const float*)d_in[3];
    const float* fc2  = (const float*)d_in[4];
    const float* fc3  = (const float*)d_in[5];
    const float* fc3b = (const float*)d_in[6];
    const float* fca  = (const float*)d_in[7];
    const float* fcab = (const float*)d_in[8];
    const float* w3   = (const float*)d_in[9];
    const float* b3   = (const float*)d_in[10];
    const float* u3   = (const float*)d_in[11];
    const float* u3b  = (const float*)d_in[12];
    const float* w4   = (const float*)d_in[13];
    const float* b4   = (const float*)d_in[14];
    const float* w5   = (const float*)d_in[15];
    const float* b5   = (const float*)d_in[16];
    const float* u5   = (const float*)d_in[17];
    const float* u5b  = (const float*)d_in[18];
    const float* fco  = (const float*)d_in[19];
    const float* fcob = (const float*)d_in[20];
    float* out = (float*)d_out;

    float *p_fwd, *p_wall, *p_ball, *p_fwh, *p_g, *p_nodes, *p_a, *p_zrh;
    cudaGetSymbolAddress((void**)&p_fwd,   d_fwd);
    cudaGetSymbolAddress((void**)&p_wall,  d_wall);
    cudaGetSymbolAddress((void**)&p_ball,  d_ball);
    cudaGetSymbolAddress((void**)&p_fwh,   d_fwh);
    cudaGetSymbolAddress((void**)&p_g,     d_g);
    cudaGetSymbolAddress((void**)&p_nodes, d_nodes);
    cudaGetSymbolAddress((void**)&p_a,     d_abuf);
    cudaGetSymbolAddress((void**)&p_zrh,   d_zrh);

    const int NOMASK = 0x7FFFFFFF;

    // weight prep
    k_wsum<<<3072, 256>>>(w3, w4, w5);
    k_bias<<<4, 256>>>(b3, u3b, b4, b5, u5b);
    k_v<<<4, 256>>>(fc3, fca);
    k_c0<<<1, 256>>>(fc3b, fca, fcab);

    // semantic branch
    gemm<MODE_NONE>(wemb, WDIM, fc2, WDIM, nullptr, 0, nullptr, 0, NOMASK, 0,
                    LD, CD, WDIM, nullptr, nullptr, nullptr, p_fwd, CD);
    gemm<MODE_NONE>(img, CD, fc1, CD, nullptr, 0, nullptr, 0, NOMASK, 0,
                    NP, CD, CD, nullptr, nullptr, nullptr, p_fwh, CD);
    k_coeff<<<NP, 256>>>();
    k_softmax<<<40, 256>>>();
    k_g<<<BT*LD, 256>>>(img);   // also seeds nodes = g

    // GGNN: per step, one fused ZRH GEMM (N=3072) + one GRU-update GEMM (K=1024)
    for (int step = 0; step < 3; ++step) {
        k_a<<<BT*LD, 256>>>(adj);
        // cols [0,1024): z = sig(a@w3s + nodes@u3 + b)
        // cols [1024,2048): rn = sig(a@w4s + nodes@u3 + b) * nodes
        // cols [2048,3072): htmp = a@w5s + b   (pass-2 skipped via n2_limit)
        gemm<MODE_ZRH>(p_a, CD, p_wall, CD, p_nodes, CD, u3, CD, CD-1, 2*CD,
                       BT*LD, 3*CD, CD, p_ball, p_nodes, nullptr, p_zrh, 3*CD);
        // nodes = (1-z)*nodes + z*tanh(rn@u5 + htmp)
        gemm<MODE_GRU2>(p_zrh + CD, 3*CD, u5, CD, nullptr, 0, nullptr, 0, NOMASK, 0,
                        BT*LD, CD, CD, nullptr, p_zrh, p_nodes, p_nodes, CD);
    }

    // out = tanh([nodes, g] @ fco^T + fco_b) — dual-K over fco column halves
    gemm<MODE_TANH>(p_nodes, CD, fco, OD, p_g, CD, fco + CD, OD, NOMASK, 0x7FFFFFFF,
                    BT*LD, OD, CD, fcob, nullptr, nullptr, out, OD);
}